// round 14
// baseline (speedup 1.0000x reference)
#include <cuda_runtime.h>
#include <cuda_bf16.h>

// Problem shape (fixed by the dataset)
#define BATCH 128
#define SEQLEN 1024
#define TAG 128

// Scratch (allocation-free rule: __device__ globals)
__device__ float g_red[BATCH];   // per-batch (logZ - score)

// ---------------- packed f32x2 helpers (Blackwell FFMA2) ----------------
__device__ __forceinline__ unsigned long long pack_f32x2(float lo, float hi) {
    unsigned long long r;
    asm("mov.b64 %0, {%1, %2};" : "=l"(r) : "f"(lo), "f"(hi));
    return r;
}
__device__ __forceinline__ unsigned long long fma2(unsigned long long a,
                                                   unsigned long long b,
                                                   unsigned long long c) {
    unsigned long long d;
    asm("fma.rn.f32x2 %0, %1, %2, %3;" : "=l"(d) : "l"(a), "l"(b), "l"(c));
    return d;
}
__device__ __forceinline__ unsigned long long add2(unsigned long long a,
                                                   unsigned long long b) {
    unsigned long long d;
    asm("add.rn.f32x2 %0, %1, %2;" : "=l"(d) : "l"(a), "l"(b));
    return d;
}
__device__ __forceinline__ float red2(unsigned long long v) {
    float lo, hi;
    asm("mov.b64 {%0, %1}, %2;" : "=f"(lo), "=f"(hi) : "l"(v));
    return lo + hi;
}

// CTA-wide named barriers at ASYMMETRIC program points: region A always holds
// fwd-combine || bwd-spread; region B fwd-spread || bwd-combine. This pins the
// two directions' FFMA bursts against each other's latency phases.
__device__ __forceinline__ void bar_a() { asm volatile("bar.sync 14, 256;" ::: "memory"); }
__device__ __forceinline__ void bar_b() { asm volatile("bar.sync 15, 256;" ::: "memory"); }

// ---- split-u spread: warp w, over u in [32w,32w+32), computes partial sums
// for outputs t = 4l..4l+3 and stores one STS.128. 8 accumulator chains.
__device__ __forceinline__ void spread(
    const float* __restrict__ vec32,             // own-warp vector slice (16B aligned)
    const unsigned long long (&ea2)[64],         // [j*16+k]: EA over (u0+2k,u0+2k+1), output j
    float* __restrict__ part, int w, int l)
{
    unsigned long long a0 = 0ull, a1 = 0ull, a2 = 0ull, a3 = 0ull;
    unsigned long long b0 = 0ull, b1 = 0ull, b2 = 0ull, b3 = 0ull;
    const ulonglong2* pp = reinterpret_cast<const ulonglong2*>(vec32);
#pragma unroll
    for (int c = 0; c < 8; c += 2) {
        ulonglong2 v = pp[c];
        a0 = fma2(v.x, ea2[0 * 16 + 2 * c], a0); a0 = fma2(v.y, ea2[0 * 16 + 2 * c + 1], a0);
        a1 = fma2(v.x, ea2[1 * 16 + 2 * c], a1); a1 = fma2(v.y, ea2[1 * 16 + 2 * c + 1], a1);
        a2 = fma2(v.x, ea2[2 * 16 + 2 * c], a2); a2 = fma2(v.y, ea2[2 * 16 + 2 * c + 1], a2);
        a3 = fma2(v.x, ea2[3 * 16 + 2 * c], a3); a3 = fma2(v.y, ea2[3 * 16 + 2 * c + 1], a3);
        ulonglong2 u = pp[c + 1];
        b0 = fma2(u.x, ea2[0 * 16 + 2 * c + 2], b0); b0 = fma2(u.y, ea2[0 * 16 + 2 * c + 3], b0);
        b1 = fma2(u.x, ea2[1 * 16 + 2 * c + 2], b1); b1 = fma2(u.y, ea2[1 * 16 + 2 * c + 3], b1);
        b2 = fma2(u.x, ea2[2 * 16 + 2 * c + 2], b2); b2 = fma2(u.y, ea2[2 * 16 + 2 * c + 3], b2);
        b3 = fma2(u.x, ea2[3 * 16 + 2 * c + 2], b3); b3 = fma2(u.y, ea2[3 * 16 + 2 * c + 3], b3);
    }
    a0 = add2(a0, b0); a1 = add2(a1, b1); a2 = add2(a2, b2); a3 = add2(a3, b3);
    float4 po;
    po.x = red2(a0); po.y = red2(a1); po.z = red2(a2); po.w = red2(a3);
    *reinterpret_cast<float4*>(part + w * TAG + 4 * l) = po;
}

// ---------------- fwd body(w): BAR_A; combine step w+1; BAR_B; spread ------
// Slot (w mod 4) holds (ey_{w+1}, m_{w+1}); after consumption it is refilled
// with step w+5's values from raws loaded in body(w-1)'s region B.
template <int SLOT, bool RENORM, bool PREP>
__device__ __forceinline__ void fwd_body(
    int wdx, int w, int l, int t, float& alpha, int& kacc,
    float (&eyp)[4], float (&mr)[4], float& yp_raw, float& m_raw,
    const float* __restrict__ yprow, const float* __restrict__ mrow,
    const unsigned long long (&ea2)[64],
    float* __restrict__ asmv, float* __restrict__ part, float* __restrict__ sb)
{
    bar_a();
    // ---- region A: combine ----
    float k1 = eyp[SLOT], k2 = 1.0f;
    if (RENORM) {   // exact power-of-2 rescale; sb published >=2 bars ago
        int kb = (__float_as_int(sb[0]) >> 23) & 0xff;
        float invc = __int_as_float((254 - kb) << 23);
        kacc += 127 - kb;
        k1 *= invc; k2 = invc;
    }
    float s = (part[t] + part[TAG + t]) + (part[2 * TAG + t] + part[3 * TAG + t]);
    alpha = (mr[SLOT] > 0.5f) ? s * k1 : alpha * k2;
    asmv[t] = alpha;
    if (PREP && t == 0) sb[0] = alpha;
    eyp[SLOT] = (wdx <= 507) ? __expf(yp_raw) : 0.0f;   // step wdx+5
    mr[SLOT]  = m_raw;
    bar_b();
    // ---- region B: spread for step wdx+2 (reads alpha_{wdx+1}) ----
    spread(asmv + 32 * w, ea2, part, w, l);
    bool nv = (wdx + 6 <= 512);
    yp_raw = nv ? __ldg(yprow + (wdx + 6) * TAG) : 0.0f;
    m_raw  = nv ? __ldg(mrow + (wdx + 6)) : 1.0f;
}

// ---------------- bwd body(k): BAR_A; spread; BAR_B; combine ----------------
// combine(k): k=0 masked dummy, else processes step i = 1024-k, producing
// beta_{i-1} and publishing c_{i-1} = beta_{i-1} * ey_{i-1} (1 at i-1 == 512).
// Slot (k mod 4); refilled with window k+4's (mask_{1020-k}, ey-pub).
template <int SLOT, bool RENORM, bool PREP>
__device__ __forceinline__ void bwd_body(
    int k, int w, int l, int t, float& beta, int& kacc,
    float (&eyp)[4], float (&mr)[4],
    const float* __restrict__ ypb, const float* __restrict__ mrow,
    const unsigned long long (&ea2)[64],
    float* __restrict__ asmc, float* __restrict__ part, float* __restrict__ sb)
{
    bar_a();
    // ---- region A: spread for combine(k) (reads c from combine(k-1)) ----
    spread(asmc + 32 * w, ea2, part, w, l);
    bool pv  = (k <= 507);
    bool pv2 = (k <= 506);
    float m_raw  = pv  ? __ldg(mrow + (1020 - k)) : 1.0f;
    float yp_raw = pv2 ? __ldg(ypb + (size_t)(1019 - k) * TAG + t) : 0.0f;
    bar_b();
    // ---- region B: combine ----
    float K = 1.0f;
    if (RENORM) {
        int kb = (__float_as_int(sb[1]) >> 23) & 0xff;
        K = __int_as_float((254 - kb) << 23);
        kacc += 127 - kb;
    }
    float s = (part[t] + part[TAG + t]) + (part[2 * TAG + t] + part[3 * TAG + t]);
    beta = ((mr[SLOT] > 0.5f) ? s : beta) * K;
    float c = beta * eyp[SLOT];
    asmc[t] = c;
    if (PREP && t == 0) sb[1] = c;
    eyp[SLOT] = pv ? ((k == 507) ? 1.0f : __expf(yp_raw)) : 1.0f;
    mr[SLOT]  = m_raw;
}

// ---------------- main kernel: 1 CTA (256 thr) per batch -------------------
__global__ void __launch_bounds__(256, 1)
crf_main_kernel(const float* __restrict__ y_pred,
                const int* __restrict__ y_true32,
                const float* __restrict__ mask,
                const float* __restrict__ A)
{
    const int tid = threadIdx.x;
    const int sub = tid >> 7;            // 0 = forward, 1 = backward
    const int t   = tid & (TAG - 1);
    const int w   = t >> 5;
    const int l   = t & 31;
    const int b   = blockIdx.x;

    __shared__ __align__(16) float s_asm[2][TAG];     // alpha / c vectors
    __shared__ __align__(16) float s_part[2][4 * TAG];// partials (single buffer each)
    __shared__ float s_sb[2];
    __shared__ int   s_kacc[2];
    __shared__ float s_logZ;
    __shared__ int   s_is64;

    float* asmv = s_asm[sub];
    float* part = s_part[sub];
    float* sb   = s_sb;

    const float* ypb   = y_pred + (size_t)b * SEQLEN * TAG;
    const float* yprow = ypb + t;
    const float* mrow  = mask + (size_t)b * SEQLEN;

    // ---- EA block (32 u x 4 outputs) in 64 packed regs ----
    unsigned long long ea2[64];
    const int u0 = 32 * w;
    if (sub == 0) {
#pragma unroll
        for (int j = 0; j < 4; j++)
#pragma unroll
            for (int k = 0; k < 16; k++) {
                float e0 = __expf(__ldg(A + (u0 + 2 * k)     * TAG + (4 * l + j)));
                float e1 = __expf(__ldg(A + (u0 + 2 * k + 1) * TAG + (4 * l + j)));
                ea2[j * 16 + k] = pack_f32x2(e0, e1);
            }
    } else {
#pragma unroll
        for (int j = 0; j < 4; j++)
#pragma unroll
            for (int k = 0; k < 16; k++) {
                float e0 = __expf(__ldg(A + (4 * l + j) * TAG + (u0 + 2 * k)));
                float e1 = __expf(__ldg(A + (4 * l + j) * TAG + (u0 + 2 * k + 1)));
                ea2[j * 16 + k] = pack_f32x2(e0, e1);
            }
    }

    int kacc = 0;
    float eyp[4], mr[4];

    if (sub == 0) {
        // ================= FORWARD: steps 1..512 =================
        float alpha = __expf(__ldg(yprow));    // alpha_0
        asmv[t] = alpha;
        if (t == 0) sb[0] = alpha;
#pragma unroll
        for (int j = 0; j < 4; j++) {
            eyp[j] = __expf(__ldg(yprow + (1 + j) * TAG));
            mr[j]  = __ldg(mrow + (1 + j));
        }
        float yp_raw = __ldg(yprow + 5 * TAG);   // step 5 raws (slot0 refill)
        float m_raw  = __ldg(mrow + 5);
        __syncwarp();                            // own-slice visibility
        spread(asmv + 32 * w, ea2, part, w, l);  // partials for step 1

        for (int g = 0; g < 128; g++) {
            const int w4 = 4 * g;
            fwd_body<0, true,  false>(w4,     w, l, t, alpha, kacc, eyp, mr, yp_raw, m_raw, yprow, mrow, ea2, asmv, part, sb);
            fwd_body<1, false, false>(w4 + 1, w, l, t, alpha, kacc, eyp, mr, yp_raw, m_raw, yprow, mrow, ea2, asmv, part, sb);
            fwd_body<2, false, true >(w4 + 2, w, l, t, alpha, kacc, eyp, mr, yp_raw, m_raw, yprow, mrow, ea2, asmv, part, sb);
            fwd_body<3, false, false>(w4 + 3, w, l, t, alpha, kacc, eyp, mr, yp_raw, m_raw, yprow, mrow, ea2, asmv, part, sb);
        }
        if (t == 0) s_kacc[0] = kacc;
        // asmv = alpha_512 (scaled 2^-kf)
    } else {
        // ================= BACKWARD: steps 1023..513 (+1 dummy) =================
        float beta = 1.0f;
        float c0 = __expf(__ldg(ypb + (size_t)(SEQLEN - 1) * TAG + t));
        asmv[t] = c0;                           // c_1023 = ey_1023 * 1
        if (t == 0) sb[1] = c0;
        mr[0] = 0.0f;               eyp[0] = c0;   // window 0: masked dummy
        mr[1] = __ldg(mrow + 1023); eyp[1] = __expf(__ldg(ypb + (size_t)1022 * TAG + t));
        mr[2] = __ldg(mrow + 1022); eyp[2] = __expf(__ldg(ypb + (size_t)1021 * TAG + t));
        mr[3] = __ldg(mrow + 1021); eyp[3] = __expf(__ldg(ypb + (size_t)1020 * TAG + t));

        for (int g = 0; g < 128; g++) {
            const int k4 = 4 * g;
            bwd_body<0, true,  false>(k4,     w, l, t, beta, kacc, eyp, mr, ypb, mrow, ea2, asmv, part, sb);
            bwd_body<1, false, false>(k4 + 1, w, l, t, beta, kacc, eyp, mr, ypb, mrow, ea2, asmv, part, sb);
            bwd_body<2, false, true >(k4 + 2, w, l, t, beta, kacc, eyp, mr, ypb, mrow, ea2, asmv, part, sb);
            bwd_body<3, false, false>(k4 + 3, w, l, t, beta, kacc, eyp, mr, ypb, mrow, ea2, asmv, part, sb);
        }
        if (t == 0) s_kacc[1] = kacc;
        // asmv = beta_512 (scaled 2^-kb; last publish factor was 1.0)
    }

    __syncthreads();   // join halves

    // ---- logZ = log(sum_t alpha[t]*beta[t]) - (kf+kb)*ln2 ----
    if (tid < 32) {
        float v = 0.0f;
#pragma unroll
        for (int j = 0; j < 4; j++)
            v += s_asm[0][tid + 32 * j] * s_asm[1][tid + 32 * j];
#pragma unroll
        for (int o = 16; o > 0; o >>= 1)
            v += __shfl_xor_sync(0xffffffffu, v, o);
        if (tid == 0)
            s_logZ = logf(v) - (float)(s_kacc[0] + s_kacc[1]) * 0.69314718055994530942f;
    }

    // ---- path score (fused) ----
    // y_true is int32 under JAX default x64-disabled; detect genuine LE int64
    // (odd words of first 128 entries all zero <=> int64; tags are 0..127).
    if (tid == 0) s_is64 = 1;
    __syncthreads();
    if (tid < 128 && y_true32[2 * tid + 1] != 0) s_is64 = 0;
    __syncthreads();
    const int stride = s_is64 ? 2 : 1;
    const int* yt = y_true32 + (size_t)b * SEQLEN * stride;

    float acc = 0.0f;
    for (int s = tid; s < SEQLEN; s += 256) {
        int tag = yt[s * stride] & (TAG - 1);
        float m = mrow[s];
        acc += ypb[(size_t)s * TAG + tag] * m;
        if (s + 1 < SEQLEN) {
            int tag2 = yt[(s + 1) * stride] & (TAG - 1);
            acc += A[tag * TAG + tag2] * m * mrow[s + 1];
        }
    }
    float* red = &s_part[0][0];   // scratch (scan done)
    red[tid] = acc;
    __syncthreads();
    if (tid < 32) {
        float v = 0.0f;
#pragma unroll
        for (int j = 0; j < 8; j++) v += red[tid + 32 * j];
#pragma unroll
        for (int o = 16; o > 0; o >>= 1)
            v += __shfl_xor_sync(0xffffffffu, v, o);
        if (tid == 0) g_red[b] = s_logZ - v;
    }
}

// ---------------- final mean kernel ----------------
__global__ void __launch_bounds__(128, 1)
crf_final_kernel(float* __restrict__ out)
{
    const int t = threadIdx.x;
    float v = g_red[t];
    __shared__ float red[128];
    red[t] = v;
    __syncthreads();
    if (t < 32) {
        float s = red[t] + red[t + 32] + red[t + 64] + red[t + 96];
#pragma unroll
        for (int o = 16; o > 0; o >>= 1)
            s += __shfl_xor_sync(0xffffffffu, s, o);
        if (t == 0) out[0] = s * (1.0f / (float)BATCH);
    }
}

// ---------------- launch ----------------
extern "C" void kernel_launch(void* const* d_in, const int* in_sizes, int n_in,
                              void* d_out, int out_size)
{
    const float* y_pred = nullptr;
    const float* A = nullptr;
    const int* y_true = nullptr;
    const float* mask = nullptr;
    for (int i = 0; i < n_in; i++) {
        long long sz = in_sizes[i];
        if (sz == (long long)BATCH * SEQLEN * TAG) {
            y_pred = (const float*)d_in[i];
        } else if (sz == (long long)TAG * TAG) {
            A = (const float*)d_in[i];
        } else if (sz == (long long)BATCH * SEQLEN) {
            if (!y_true) y_true = (const int*)d_in[i];
            else mask = (const float*)d_in[i];
        }
    }

    crf_main_kernel<<<BATCH, 256>>>(y_pred, y_true, mask, A);
    crf_final_kernel<<<1, 128>>>((float*)d_out);
}

// round 15
// speedup vs baseline: 1.0279x; 1.0279x over previous
#include <cuda_runtime.h>
#include <cuda_bf16.h>

// Problem shape (fixed by the dataset)
#define BATCH 128
#define SEQLEN 1024
#define TAG 128
#define MID 512   // fwd: steps 1..512 -> alpha_512 ; bwd: 1023..513 -> beta_512

// Scratch (allocation-free rule: __device__ globals)
__device__ float g_red[BATCH];   // per-batch (logZ - score)

// ---------------- packed f32x2 helpers (Blackwell FFMA2) ----------------
__device__ __forceinline__ unsigned long long pack_f32x2(float lo, float hi) {
    unsigned long long r;
    asm("mov.b64 %0, {%1, %2};" : "=l"(r) : "f"(lo), "f"(hi));
    return r;
}
__device__ __forceinline__ unsigned long long fma2(unsigned long long a,
                                                   unsigned long long b,
                                                   unsigned long long c) {
    unsigned long long d;
    asm("fma.rn.f32x2 %0, %1, %2, %3;" : "=l"(d) : "l"(a), "l"(b), "l"(c));
    return d;
}
__device__ __forceinline__ unsigned long long add2(unsigned long long a,
                                                   unsigned long long b) {
    unsigned long long d;
    asm("add.rn.f32x2 %0, %1, %2;" : "=l"(d) : "l"(a), "l"(b));
    return d;
}
__device__ __forceinline__ float red2(unsigned long long v) {
    float lo, hi;
    asm("mov.b64 {%0, %1}, %2;" : "=f"(lo), "=f"(hi) : "l"(v));
    return lo + hi;
}

// Named barrier over one 128-thread half (fwd id=1, bwd id=2).
__device__ __forceinline__ void hbar(int id) {
    asm volatile("bar.sync %0, %1;" :: "r"(id), "r"(128) : "memory");
}

// ---- split-u spread with REGISTER-RESIDENT input: warp w's slice
// u in [32w,32w+32) lives in its own lanes' `val` registers; distribute via
// shfl (no STS/syncwarp/LDS on the chain). Computes partials for outputs
// t = 4l..4l+3, one STS.128. 8 accumulator chains.
__device__ __forceinline__ void spread_shfl(
    float val,
    const unsigned long long (&ea2)[64],   // [j*16+k]: EA over (u0+2k,u0+2k+1), output j
    float* __restrict__ part, int w, int l)
{
    unsigned long long a0 = 0ull, a1 = 0ull, a2 = 0ull, a3 = 0ull;
    unsigned long long b0 = 0ull, b1 = 0ull, b2 = 0ull, b3 = 0ull;
#pragma unroll
    for (int c = 0; c < 16; c += 2) {
        float x0 = __shfl_sync(0xffffffffu, val, 2 * c);
        float x1 = __shfl_sync(0xffffffffu, val, 2 * c + 1);
        unsigned long long v = pack_f32x2(x0, x1);
        a0 = fma2(v, ea2[0 * 16 + c], a0);
        a1 = fma2(v, ea2[1 * 16 + c], a1);
        a2 = fma2(v, ea2[2 * 16 + c], a2);
        a3 = fma2(v, ea2[3 * 16 + c], a3);
        float y0 = __shfl_sync(0xffffffffu, val, 2 * c + 2);
        float y1 = __shfl_sync(0xffffffffu, val, 2 * c + 3);
        unsigned long long u = pack_f32x2(y0, y1);
        b0 = fma2(u, ea2[0 * 16 + c + 1], b0);
        b1 = fma2(u, ea2[1 * 16 + c + 1], b1);
        b2 = fma2(u, ea2[2 * 16 + c + 1], b2);
        b3 = fma2(u, ea2[3 * 16 + c + 1], b3);
    }
    a0 = add2(a0, b0); a1 = add2(a1, b1); a2 = add2(a2, b2); a3 = add2(a3, b3);
    float4 po;
    po.x = red2(a0); po.y = red2(a1); po.z = red2(a2); po.w = red2(a3);
    *reinterpret_cast<float4*>(part + w * TAG + 4 * l) = po;
}

// ---------------- forward step: alpha = m ? (EA^T alpha)*ey : alpha --------
// One named barrier per step. Vector handoff is register-resident (shfl).
// Renorm factors computed BEFORE the spread (sb >=1 bar old); prefetch LDGs
// after the spread; blend uses precomputed k1/k2 (all exact).
template <int SLOT, int BUF, bool RENORM, bool PREP>
__device__ __forceinline__ void fwd_step(
    int i, int w, int l, int t, float& alpha, int& kacc,
    float (&eyp)[4], float (&mr)[4],
    const float* __restrict__ yprow, const float* __restrict__ mrow,
    const unsigned long long (&ea2)[64],
    float* __restrict__ partb, float* __restrict__ sb)
{
    float k1 = eyp[SLOT], k2 = 1.0f;
    if (RENORM) {   // exact power-of-2 rescale
        int kb = (__float_as_int(sb[0]) >> 23) & 0xff;
        float invc = __int_as_float((254 - kb) << 23);
        kacc += 127 - kb;
        k1 *= invc; k2 = invc;
    }

    float* part = partb + BUF * 4 * TAG;
    spread_shfl(alpha, ea2, part, w, l);

    // prefetch step i+4's raw y_pred/mask (after spread issue, before bar)
    float yp_n = 0.0f, m_n = 1.0f;
    bool pf = (i + 4 <= MID);
    if (pf) {
        yp_n = __ldg(yprow + (i + 4) * TAG);
        m_n  = __ldg(mrow + (i + 4));
    }
    hbar(1);

    float s = (part[t] + part[TAG + t]) + (part[2 * TAG + t] + part[3 * TAG + t]);
    alpha = (mr[SLOT] > 0.5f) ? s * k1 : alpha * k2;
    if (PREP && t == 0) sb[0] = alpha;
    eyp[SLOT] = pf ? __expf(yp_n) : 0.0f;
    mr[SLOT]  = m_n;
}

// ---------------- backward step: beta = m ? EA@(ey_i*beta) : beta ----------
// c = ey_i * beta_i is the register-resident spread vector.
template <int SLOT, int BUF, bool RENORM, bool PREP>
__device__ __forceinline__ void bwd_step(
    int i, int w, int l, int t, float& beta, float& c, int& kacc,
    float (&eypub)[4], float (&mr)[4],
    const float* __restrict__ yprow, const float* __restrict__ mrow,
    const unsigned long long (&ea2)[64],
    float* __restrict__ partb, float* __restrict__ sb)
{
    float k2 = 1.0f;
    if (RENORM) {
        int kb = (__float_as_int(sb[1]) >> 23) & 0xff;
        k2 = __int_as_float((254 - kb) << 23);
        kacc += 127 - kb;
    }

    float* part = partb + BUF * 4 * TAG;
    spread_shfl(c, ea2, part, w, l);

    // prefetch step i-4's raw (mask, y_pred for ey_pub)
    float yp_n = 0.0f, m_n = 1.0f;
    bool pf = (i - 4 >= MID + 1);
    bool pfe = (i - 4 > MID + 1);
    if (pf) {
        m_n = __ldg(mrow + (i - 4));
        if (pfe) yp_n = __ldg(yprow + (i - 5) * TAG);
    }
    hbar(2);

    float s = (part[t] + part[TAG + t]) + (part[2 * TAG + t] + part[3 * TAG + t]);
    beta = (mr[SLOT] > 0.5f) ? s * k2 : beta * k2;
    c = beta * eypub[SLOT];
    if (PREP && t == 0) sb[1] = c;
    eypub[SLOT] = pfe ? __expf(yp_n) : 1.0f;
    mr[SLOT]    = m_n;
}

// ---------------- main kernel: 1 CTA (256 thr) per batch -------------------
__global__ void __launch_bounds__(256, 1)
crf_main_kernel(const float* __restrict__ y_pred,
                const int* __restrict__ y_true32,
                const float* __restrict__ mask,
                const float* __restrict__ A)
{
    const int tid = threadIdx.x;
    const int sub = tid >> 7;            // 0 = forward, 1 = backward
    const int t   = tid & (TAG - 1);
    const int w   = t >> 5;
    const int l   = t & 31;
    const int b   = blockIdx.x;

    __shared__ __align__(16) float s_asm[2][TAG];       // final vectors only
    __shared__ __align__(16) float s_part[2][2 * 4 * TAG];  // [sub][buf*4*TAG]
    __shared__ float s_sb[2];
    __shared__ int   s_kacc[2];
    __shared__ float s_logZ;
    __shared__ int   s_is64;

    float* partb = s_part[sub];
    float* sb    = s_sb;

    const float* ypb   = y_pred + (size_t)b * SEQLEN * TAG;
    const float* yprow = ypb + t;
    const float* mrow  = mask + (size_t)b * SEQLEN;

    // ---- EA block (32 u x 4 outputs) in 64 packed regs ----
    unsigned long long ea2[64];
    const int u0 = 32 * w;
    if (sub == 0) {
#pragma unroll
        for (int j = 0; j < 4; j++)
#pragma unroll
            for (int k = 0; k < 16; k++) {
                float e0 = __expf(__ldg(A + (u0 + 2 * k)     * TAG + (4 * l + j)));
                float e1 = __expf(__ldg(A + (u0 + 2 * k + 1) * TAG + (4 * l + j)));
                ea2[j * 16 + k] = pack_f32x2(e0, e1);
            }
    } else {
#pragma unroll
        for (int j = 0; j < 4; j++)
#pragma unroll
            for (int k = 0; k < 16; k++) {
                float e0 = __expf(__ldg(A + (4 * l + j) * TAG + (u0 + 2 * k)));
                float e1 = __expf(__ldg(A + (4 * l + j) * TAG + (u0 + 2 * k + 1)));
                ea2[j * 16 + k] = pack_f32x2(e0, e1);
            }
    }

    int kacc = 0;
    float eyp[4], mr[4];

    if (sub == 0) {
        // ================= FORWARD: steps 1..512 =================
        float alpha = __expf(__ldg(yprow));    // alpha_0 (register-resident)
        if (t == 0) sb[0] = alpha;
#pragma unroll
        for (int j = 0; j < 4; j++) {
            eyp[j] = __expf(__ldg(yprow + (1 + j) * TAG));
            mr[j]  = __ldg(mrow + (1 + j));
        }
        hbar(1);   // sb visibility before window 0's renorm read

        for (int i = 1; i <= MID - 3; i += 4) {   // 128 groups; PREP at slot 2
            fwd_step<0, 0, true,  false>(i,     w, l, t, alpha, kacc, eyp, mr, yprow, mrow, ea2, partb, sb);
            fwd_step<1, 1, false, false>(i + 1, w, l, t, alpha, kacc, eyp, mr, yprow, mrow, ea2, partb, sb);
            fwd_step<2, 0, false, true >(i + 2, w, l, t, alpha, kacc, eyp, mr, yprow, mrow, ea2, partb, sb);
            fwd_step<3, 1, false, false>(i + 3, w, l, t, alpha, kacc, eyp, mr, yprow, mrow, ea2, partb, sb);
        }
        if (t == 0) s_kacc[0] = kacc;
        s_asm[0][t] = alpha;                   // publish alpha_512 for the join
    } else {
        // ================= BACKWARD: steps 1023..513 =================
        float beta = 1.0f;
        float c = __expf(__ldg(yprow + (SEQLEN - 1) * TAG));   // c_1023
        if (t == 0) sb[1] = c;
#pragma unroll
        for (int j = 0; j < 4; j++) {
            mr[j]  = __ldg(mrow + (SEQLEN - 1 - j));
            eyp[j] = __expf(__ldg(yprow + (SEQLEN - 2 - j) * TAG));
        }
        hbar(2);   // sb visibility before window 0's renorm read

        // phase-shift: one dummy spread (writes buffer 0, overwritten by the
        // first real spread before any post-hbar read; values never escape).
        spread_shfl(c, ea2, partb, w, l);

        for (int i = SEQLEN - 1; i >= MID + 7; i -= 4) {   // 127 groups: 1023..516
            bwd_step<0, 0, true,  false>(i,     w, l, t, beta, c, kacc, eyp, mr, yprow, mrow, ea2, partb, sb);
            bwd_step<1, 1, false, false>(i - 1, w, l, t, beta, c, kacc, eyp, mr, yprow, mrow, ea2, partb, sb);
            bwd_step<2, 0, false, true >(i - 2, w, l, t, beta, c, kacc, eyp, mr, yprow, mrow, ea2, partb, sb);
            bwd_step<3, 1, false, false>(i - 3, w, l, t, beta, c, kacc, eyp, mr, yprow, mrow, ea2, partb, sb);
        }
        // remainder: steps 515, 514, 513
        bwd_step<0, 0, true,  false>(MID + 3, w, l, t, beta, c, kacc, eyp, mr, yprow, mrow, ea2, partb, sb);
        bwd_step<1, 1, false, false>(MID + 2, w, l, t, beta, c, kacc, eyp, mr, yprow, mrow, ea2, partb, sb);
        bwd_step<2, 0, false, true >(MID + 1, w, l, t, beta, c, kacc, eyp, mr, yprow, mrow, ea2, partb, sb);
        if (t == 0) s_kacc[1] = kacc;
        s_asm[1][t] = beta;                    // beta_512 (publish factor was 1)
    }

    __syncthreads();   // join halves

    // ---- logZ = log(sum_t a_mid[t]*b_mid[t]) - (kf+kb)*ln2 ----
    if (tid < 32) {
        float v = 0.0f;
#pragma unroll
        for (int j = 0; j < 4; j++)
            v += s_asm[0][tid + 32 * j] * s_asm[1][tid + 32 * j];
#pragma unroll
        for (int o = 16; o > 0; o >>= 1)
            v += __shfl_xor_sync(0xffffffffu, v, o);
        if (tid == 0)
            s_logZ = logf(v) - (float)(s_kacc[0] + s_kacc[1]) * 0.69314718055994530942f;
    }

    // ---- path score (fused) ----
    // y_true is int32 under JAX default x64-disabled; detect genuine LE int64
    // (odd words of first 128 entries all zero <=> int64; tags are 0..127).
    if (tid == 0) s_is64 = 1;
    __syncthreads();
    if (tid < 128 && y_true32[2 * tid + 1] != 0) s_is64 = 0;
    __syncthreads();
    const int stride = s_is64 ? 2 : 1;
    const int* yt = y_true32 + (size_t)b * SEQLEN * stride;

    float acc = 0.0f;
    for (int s = tid; s < SEQLEN; s += 256) {
        int tag = yt[s * stride] & (TAG - 1);
        float m = mrow[s];
        acc += ypb[(size_t)s * TAG + tag] * m;
        if (s + 1 < SEQLEN) {
            int tag2 = yt[(s + 1) * stride] & (TAG - 1);
            acc += A[tag * TAG + tag2] * m * mrow[s + 1];
        }
    }
    float* red = &s_part[0][0];   // scratch (scan done)
    red[tid] = acc;
    __syncthreads();
    if (tid < 32) {
        float v = 0.0f;
#pragma unroll
        for (int j = 0; j < 8; j++) v += red[tid + 32 * j];
#pragma unroll
        for (int o = 16; o > 0; o >>= 1)
            v += __shfl_xor_sync(0xffffffffu, v, o);
        if (tid == 0) g_red[b] = s_logZ - v;
    }
}

// ---------------- final mean kernel ----------------
__global__ void __launch_bounds__(128, 1)
crf_final_kernel(float* __restrict__ out)
{
    const int t = threadIdx.x;
    float v = g_red[t];
    __shared__ float red[128];
    red[t] = v;
    __syncthreads();
    if (t < 32) {
        float s = red[t] + red[t + 32] + red[t + 64] + red[t + 96];
#pragma unroll
        for (int o = 16; o > 0; o >>= 1)
            s += __shfl_xor_sync(0xffffffffu, s, o);
        if (t == 0) out[0] = s * (1.0f / (float)BATCH);
    }
}

// ---------------- launch ----------------
extern "C" void kernel_launch(void* const* d_in, const int* in_sizes, int n_in,
                              void* d_out, int out_size)
{
    const float* y_pred = nullptr;
    const float* A = nullptr;
    const int* y_true = nullptr;
    const float* mask = nullptr;
    for (int i = 0; i < n_in; i++) {
        long long sz = in_sizes[i];
        if (sz == (long long)BATCH * SEQLEN * TAG) {
            y_pred = (const float*)d_in[i];
        } else if (sz == (long long)TAG * TAG) {
            A = (const float*)d_in[i];
        } else if (sz == (long long)BATCH * SEQLEN) {
            if (!y_true) y_true = (const int*)d_in[i];
            else mask = (const float*)d_in[i];
        }
    }

    crf_main_kernel<<<BATCH, 256>>>(y_pred, y_true, mask, A);
    crf_final_kernel<<<1, 128>>>((float*)d_out);
}

// round 16
// speedup vs baseline: 1.1877x; 1.1554x over previous
#include <cuda_runtime.h>
#include <cuda_bf16.h>

// Problem shape (fixed by the dataset)
#define BATCH 128
#define SEQLEN 1024
#define TAG 128
#define MID 512   // fwd: steps 1..512 -> alpha_512 ; bwd: 1023..513 -> beta_512

// Scratch (allocation-free rule: __device__ globals)
__device__ float g_red[BATCH];        // per-batch (logZ - score)
__device__ int   g_count = 0;         // last-block counter (reset by the last block)

// ---------------- packed f32x2 helpers (Blackwell FFMA2) ----------------
__device__ __forceinline__ unsigned long long pack_f32x2(float lo, float hi) {
    unsigned long long r;
    asm("mov.b64 %0, {%1, %2};" : "=l"(r) : "f"(lo), "f"(hi));
    return r;
}
__device__ __forceinline__ unsigned long long fma2(unsigned long long a,
                                                   unsigned long long b,
                                                   unsigned long long c) {
    unsigned long long d;
    asm("fma.rn.f32x2 %0, %1, %2, %3;" : "=l"(d) : "l"(a), "l"(b), "l"(c));
    return d;
}
__device__ __forceinline__ unsigned long long add2(unsigned long long a,
                                                   unsigned long long b) {
    unsigned long long d;
    asm("add.rn.f32x2 %0, %1, %2;" : "=l"(d) : "l"(a), "l"(b));
    return d;
}
__device__ __forceinline__ float red2(unsigned long long v) {
    float lo, hi;
    asm("mov.b64 {%0, %1}, %2;" : "=f"(lo), "=f"(hi) : "l"(v));
    return lo + hi;
}

// Named barrier over one 128-thread half (fwd id=1, bwd id=2).
__device__ __forceinline__ void hbar(int id) {
    asm volatile("bar.sync %0, %1;" :: "r"(id), "r"(128) : "memory");
}

// ---- split-u spread: warp w, over u in [32w,32w+32), computes partial sums
// for outputs t = 4l..4l+3 and stores one STS.128. 8 accumulator chains.
__device__ __forceinline__ void spread(
    const float* __restrict__ vec32,             // own-warp vector slice (16B aligned)
    const unsigned long long (&ea2)[64],         // [j*16+k]: EA over (u0+2k,u0+2k+1), output j
    float* __restrict__ part, int w, int l)
{
    unsigned long long a0 = 0ull, a1 = 0ull, a2 = 0ull, a3 = 0ull;
    unsigned long long b0 = 0ull, b1 = 0ull, b2 = 0ull, b3 = 0ull;
    const ulonglong2* pp = reinterpret_cast<const ulonglong2*>(vec32);
#pragma unroll
    for (int c = 0; c < 8; c += 2) {
        ulonglong2 v = pp[c];
        a0 = fma2(v.x, ea2[0 * 16 + 2 * c], a0); a0 = fma2(v.y, ea2[0 * 16 + 2 * c + 1], a0);
        a1 = fma2(v.x, ea2[1 * 16 + 2 * c], a1); a1 = fma2(v.y, ea2[1 * 16 + 2 * c + 1], a1);
        a2 = fma2(v.x, ea2[2 * 16 + 2 * c], a2); a2 = fma2(v.y, ea2[2 * 16 + 2 * c + 1], a2);
        a3 = fma2(v.x, ea2[3 * 16 + 2 * c], a3); a3 = fma2(v.y, ea2[3 * 16 + 2 * c + 1], a3);
        ulonglong2 u = pp[c + 1];
        b0 = fma2(u.x, ea2[0 * 16 + 2 * c + 2], b0); b0 = fma2(u.y, ea2[0 * 16 + 2 * c + 3], b0);
        b1 = fma2(u.x, ea2[1 * 16 + 2 * c + 2], b1); b1 = fma2(u.y, ea2[1 * 16 + 2 * c + 3], b1);
        b2 = fma2(u.x, ea2[2 * 16 + 2 * c + 2], b2); b2 = fma2(u.y, ea2[2 * 16 + 2 * c + 3], b2);
        b3 = fma2(u.x, ea2[3 * 16 + 2 * c + 2], b3); b3 = fma2(u.y, ea2[3 * 16 + 2 * c + 3], b3);
    }
    a0 = add2(a0, b0); a1 = add2(a1, b1); a2 = add2(a2, b2); a3 = add2(a3, b3);
    float4 po;
    po.x = red2(a0); po.y = red2(a1); po.z = red2(a2); po.w = red2(a3);
    *reinterpret_cast<float4*>(part + w * TAG + 4 * l) = po;
}

// ---------------- forward step: alpha = m ? (EA^T alpha)*ey : alpha --------
template <int SLOT, int BUF, bool RENORM, bool PREP>
__device__ __forceinline__ void fwd_step(
    int i, int w, int l, int t, float& alpha, int& kacc,
    float (&eyp)[4], float (&mr)[4],
    const float* __restrict__ yprow, const float* __restrict__ mrow,
    const unsigned long long (&ea2)[64],
    float* __restrict__ asmv, float* __restrict__ partb, float* __restrict__ sb)
{
    // renorm factors, fully off the post-barrier chain (sb >=1 bar old)
    float k1 = eyp[SLOT], k2 = 1.0f;
    if (RENORM) {
        int kb = (__float_as_int(sb[0]) >> 23) & 0xff;
        float invc = __int_as_float((254 - kb) << 23);   // exact 2^(127-kb)
        kacc += 127 - kb;
        k1 *= invc; k2 = invc;
    }

    float* part = partb + BUF * 4 * TAG;
    spread(asmv + 32 * w, ea2, part, w, l);

    // prefetch step i+4's raw y_pred/mask (after spread issue, before bar)
    float yp_n = 0.0f, m_n = 1.0f;
    bool pf = (i + 4 <= MID);
    if (pf) {
        yp_n = __ldg(yprow + (i + 4) * TAG);
        m_n  = __ldg(mrow + (i + 4));
    }
    hbar(1);

    float s = (part[t] + part[TAG + t]) + (part[2 * TAG + t] + part[3 * TAG + t]);
    alpha = (mr[SLOT] > 0.5f) ? s * k1 : alpha * k2;
    asmv[t] = alpha;
    if (PREP && t == 0) sb[0] = alpha;
    eyp[SLOT] = pf ? __expf(yp_n) : 0.0f;
    mr[SLOT]  = m_n;
    __syncwarp();
}

// ---------------- backward step: beta = m ? EA@(ey_i*beta) : beta ----------
template <int SLOT, int BUF, bool RENORM, bool PREP>
__device__ __forceinline__ void bwd_step(
    int i, int w, int l, int t, float& beta, float& c, int& kacc,
    float (&eypub)[4], float (&mr)[4],
    const float* __restrict__ yprow, const float* __restrict__ mrow,
    const unsigned long long (&ea2)[64],
    float* __restrict__ asmv, float* __restrict__ partb, float* __restrict__ sb)
{
    float k2 = 1.0f;
    if (RENORM) {
        int kb = (__float_as_int(sb[1]) >> 23) & 0xff;
        k2 = __int_as_float((254 - kb) << 23);
        kacc += 127 - kb;
    }

    float* part = partb + BUF * 4 * TAG;
    spread(asmv + 32 * w, ea2, part, w, l);

    // prefetch step i-4's raw (mask, y_pred for ey_pub)
    float yp_n = 0.0f, m_n = 1.0f;
    bool pf = (i - 4 >= MID + 1);
    bool pfe = (i - 4 > MID + 1);
    if (pf) {
        m_n = __ldg(mrow + (i - 4));
        if (pfe) yp_n = __ldg(yprow + (i - 5) * TAG);
    }
    hbar(2);

    float s = (part[t] + part[TAG + t]) + (part[2 * TAG + t] + part[3 * TAG + t]);
    beta = (mr[SLOT] > 0.5f) ? s * k2 : beta * k2;
    c = beta * eypub[SLOT];
    asmv[t] = c;
    if (PREP && t == 0) sb[1] = c;
    eypub[SLOT] = pfe ? __expf(yp_n) : 1.0f;
    mr[SLOT]    = m_n;
    __syncwarp();
}

// ---------------- main kernel: 1 CTA (256 thr) per batch -------------------
__global__ void __launch_bounds__(256, 1)
crf_main_kernel(const float* __restrict__ y_pred,
                const int* __restrict__ y_true32,
                const float* __restrict__ mask,
                const float* __restrict__ A,
                float* __restrict__ out)
{
    const int tid = threadIdx.x;
    const int sub = tid >> 7;            // 0 = forward, 1 = backward
    const int t   = tid & (TAG - 1);
    const int w   = t >> 5;
    const int l   = t & 31;
    const int b   = blockIdx.x;

    __shared__ __align__(16) float s_asm[2][TAG];
    __shared__ __align__(16) float s_part[2][2 * 4 * TAG];  // [sub][buf*4*TAG]
    __shared__ float s_sb[2];
    __shared__ int   s_kacc[2];
    __shared__ float s_logZ;
    __shared__ int   s_is64;
    __shared__ int   s_last;

    float* asmv  = s_asm[sub];
    float* partb = s_part[sub];
    float* sb    = s_sb;

    const float* ypb   = y_pred + (size_t)b * SEQLEN * TAG;
    const float* yprow = ypb + t;
    const float* mrow  = mask + (size_t)b * SEQLEN;

    // ---- EA block (32 u x 4 outputs) in 64 packed regs ----
    unsigned long long ea2[64];
    const int u0 = 32 * w;
    if (sub == 0) {
#pragma unroll
        for (int j = 0; j < 4; j++)
#pragma unroll
            for (int k = 0; k < 16; k++) {
                float e0 = __expf(__ldg(A + (u0 + 2 * k)     * TAG + (4 * l + j)));
                float e1 = __expf(__ldg(A + (u0 + 2 * k + 1) * TAG + (4 * l + j)));
                ea2[j * 16 + k] = pack_f32x2(e0, e1);
            }
    } else {
#pragma unroll
        for (int j = 0; j < 4; j++)
#pragma unroll
            for (int k = 0; k < 16; k++) {
                float e0 = __expf(__ldg(A + (4 * l + j) * TAG + (u0 + 2 * k)));
                float e1 = __expf(__ldg(A + (4 * l + j) * TAG + (u0 + 2 * k + 1)));
                ea2[j * 16 + k] = pack_f32x2(e0, e1);
            }
    }

    int kacc = 0;
    float eyp[4], mr[4];

    if (sub == 0) {
        // ================= FORWARD: steps 1..512 =================
        float alpha = __expf(__ldg(yprow));    // alpha_0
        asmv[t] = alpha;
        if (t == 0) sb[0] = alpha;
#pragma unroll
        for (int j = 0; j < 4; j++) {
            eyp[j] = __expf(__ldg(yprow + (1 + j) * TAG));
            mr[j]  = __ldg(mrow + (1 + j));
        }
        hbar(1);   // cross-warp visibility of sb before window 0's early read

        for (int i = 1; i <= MID - 3; i += 4) {   // 128 groups; PREP at slot 2
            fwd_step<0, 0, true,  false>(i,     w, l, t, alpha, kacc, eyp, mr, yprow, mrow, ea2, asmv, partb, sb);
            fwd_step<1, 1, false, false>(i + 1, w, l, t, alpha, kacc, eyp, mr, yprow, mrow, ea2, asmv, partb, sb);
            fwd_step<2, 0, false, true >(i + 2, w, l, t, alpha, kacc, eyp, mr, yprow, mrow, ea2, asmv, partb, sb);
            fwd_step<3, 1, false, false>(i + 3, w, l, t, alpha, kacc, eyp, mr, yprow, mrow, ea2, asmv, partb, sb);
        }
        if (t == 0) s_kacc[0] = kacc;
        // asmv holds alpha_512
    } else {
        // ================= BACKWARD: steps 1023..513 =================
        float beta = 1.0f;
        float c = __expf(__ldg(yprow + (SEQLEN - 1) * TAG));   // c_1023
        asmv[t] = c;
        if (t == 0) sb[1] = c;
#pragma unroll
        for (int j = 0; j < 4; j++) {
            mr[j]  = __ldg(mrow + (SEQLEN - 1 - j));
            eyp[j] = __expf(__ldg(yprow + (SEQLEN - 2 - j) * TAG));
        }
        hbar(2);   // cross-warp visibility of sb before window 0's early read

        // phase-shift: one dummy spread so bwd's FFMA bursts land inside fwd's
        // barrier/LDS windows. Junk input flows only into partial slots
        // overwritten by the first real spread before any post-hbar read.
        spread(partb + 4 * TAG + 32 * w, ea2, partb, w, l);

        for (int i = SEQLEN - 1; i >= MID + 7; i -= 4) {   // 127 groups: 1023..516
            bwd_step<0, 0, true,  false>(i,     w, l, t, beta, c, kacc, eyp, mr, yprow, mrow, ea2, asmv, partb, sb);
            bwd_step<1, 1, false, false>(i - 1, w, l, t, beta, c, kacc, eyp, mr, yprow, mrow, ea2, asmv, partb, sb);
            bwd_step<2, 0, false, true >(i - 2, w, l, t, beta, c, kacc, eyp, mr, yprow, mrow, ea2, asmv, partb, sb);
            bwd_step<3, 1, false, false>(i - 3, w, l, t, beta, c, kacc, eyp, mr, yprow, mrow, ea2, asmv, partb, sb);
        }
        // remainder: steps 515, 514, 513
        bwd_step<0, 0, true,  false>(MID + 3, w, l, t, beta, c, kacc, eyp, mr, yprow, mrow, ea2, asmv, partb, sb);
        bwd_step<1, 1, false, false>(MID + 2, w, l, t, beta, c, kacc, eyp, mr, yprow, mrow, ea2, asmv, partb, sb);
        bwd_step<2, 0, false, true >(MID + 1, w, l, t, beta, c, kacc, eyp, mr, yprow, mrow, ea2, asmv, partb, sb);
        if (t == 0) s_kacc[1] = kacc;
        // asmv holds beta_512 (ey_pub of step 513 was 1)
    }

    __syncthreads();   // join halves

    // ---- logZ = log(sum_t a_mid[t]*b_mid[t]) - (kf+kb)*ln2 ----
    if (tid < 32) {
        float v = 0.0f;
#pragma unroll
        for (int j = 0; j < 4; j++)
            v += s_asm[0][tid + 32 * j] * s_asm[1][tid + 32 * j];
#pragma unroll
        for (int o = 16; o > 0; o >>= 1)
            v += __shfl_xor_sync(0xffffffffu, v, o);
        if (tid == 0)
            s_logZ = logf(v) - (float)(s_kacc[0] + s_kacc[1]) * 0.69314718055994530942f;
    }

    // ---- path score (fused) ----
    // y_true is int32 under JAX default x64-disabled; detect genuine LE int64
    // (odd words of first 128 entries all zero <=> int64; tags are 0..127).
    if (tid == 0) s_is64 = 1;
    __syncthreads();
    if (tid < 128 && y_true32[2 * tid + 1] != 0) s_is64 = 0;
    __syncthreads();
    const int stride = s_is64 ? 2 : 1;
    const int* yt = y_true32 + (size_t)b * SEQLEN * stride;

    float acc = 0.0f;
    for (int s = tid; s < SEQLEN; s += 256) {
        int tag = yt[s * stride] & (TAG - 1);
        float m = mrow[s];
        acc += ypb[(size_t)s * TAG + tag] * m;
        if (s + 1 < SEQLEN) {
            int tag2 = yt[(s + 1) * stride] & (TAG - 1);
            acc += A[tag * TAG + tag2] * m * mrow[s + 1];
        }
    }
    float* red = &s_part[0][0];   // scratch (scan done)
    red[tid] = acc;
    __syncthreads();
    if (tid < 32) {
        float v = 0.0f;
#pragma unroll
        for (int j = 0; j < 8; j++) v += red[tid + 32 * j];
#pragma unroll
        for (int o = 16; o > 0; o >>= 1)
            v += __shfl_xor_sync(0xffffffffu, v, o);
        if (tid == 0) {
            g_red[b] = s_logZ - v;
            __threadfence();
            int done = atomicAdd(&g_count, 1);
            s_last = (done == BATCH - 1) ? 1 : 0;
        }
    }
    __syncthreads();

    // ---- last block: deterministic final mean over g_red, reset counter ----
    if (s_last) {
        __threadfence();   // acquire: make all g_red writes visible
        float v = (tid < 128) ? *((volatile float*)&g_red[tid]) : 0.0f;
        red[tid] = v;
        __syncthreads();
        if (tid < 32) {
            float s = red[tid] + red[tid + 32] + red[tid + 64] + red[tid + 96];
#pragma unroll
            for (int o = 16; o > 0; o >>= 1)
                s += __shfl_xor_sync(0xffffffffu, s, o);
            if (tid == 0) {
                out[0] = s * (1.0f / (float)BATCH);
                __threadfence();
                g_count = 0;   // replay-safe: restore initial device state
            }
        }
    }
}

// ---------------- launch ----------------
extern "C" void kernel_launch(void* const* d_in, const int* in_sizes, int n_in,
                              void* d_out, int out_size)
{
    const float* y_pred = nullptr;
    const float* A = nullptr;
    const int* y_true = nullptr;
    const float* mask = nullptr;
    for (int i = 0; i < n_in; i++) {
        long long sz = in_sizes[i];
        if (sz == (long long)BATCH * SEQLEN * TAG) {
            y_pred = (const float*)d_in[i];
        } else if (sz == (long long)TAG * TAG) {
            A = (const float*)d_in[i];
        } else if (sz == (long long)BATCH * SEQLEN) {
            if (!y_true) y_true = (const int*)d_in[i];
            else mask = (const float*)d_in[i];
        }
    }

    crf_main_kernel<<<BATCH, 256>>>(y_pred, y_true, mask, A, (float*)d_out);
}

// round 17
// speedup vs baseline: 1.2837x; 1.0809x over previous
#include <cuda_runtime.h>
#include <cuda_bf16.h>

// Problem shape (fixed by the dataset)
#define BATCH 128
#define SEQLEN 1024
#define TAG 128
#define MID 512   // fwd: steps 1..512 -> alpha_512 ; bwd: 1023..513 -> beta_512

// Scratch (allocation-free rule: __device__ globals)
__device__ float g_red[BATCH];        // per-batch (logZ - score)
__device__ int   g_count = 0;         // last-block counter (reset by the last block)

// ---------------- packed f32x2 helpers (Blackwell FFMA2) ----------------
__device__ __forceinline__ unsigned long long pack_f32x2(float lo, float hi) {
    unsigned long long r;
    asm("mov.b64 %0, {%1, %2};" : "=l"(r) : "f"(lo), "f"(hi));
    return r;
}
__device__ __forceinline__ unsigned long long fma2(unsigned long long a,
                                                   unsigned long long b,
                                                   unsigned long long c) {
    unsigned long long d;
    asm("fma.rn.f32x2 %0, %1, %2, %3;" : "=l"(d) : "l"(a), "l"(b), "l"(c));
    return d;
}
__device__ __forceinline__ unsigned long long add2(unsigned long long a,
                                                   unsigned long long b) {
    unsigned long long d;
    asm("add.rn.f32x2 %0, %1, %2;" : "=l"(d) : "l"(a), "l"(b));
    return d;
}
__device__ __forceinline__ float red2(unsigned long long v) {
    float lo, hi;
    asm("mov.b64 {%0, %1}, %2;" : "=f"(lo), "=f"(hi) : "l"(v));
    return lo + hi;
}

// Named barrier over one 128-thread half (fwd id=1, bwd id=2).
__device__ __forceinline__ void hbar(int id) {
    asm volatile("bar.sync %0, %1;" :: "r"(id), "r"(128) : "memory");
}

// ---- split-u spread: warp w, over u in [32w,32w+32), computes partial sums
// for outputs t = 4l..4l+3 and stores one STS.128. 8 accumulator chains.
__device__ __forceinline__ void spread(
    const float* __restrict__ vec32,             // own-warp vector slice (16B aligned)
    const unsigned long long (&ea2)[64],         // [j*16+k]: EA over (u0+2k,u0+2k+1), output j
    float* __restrict__ part, int w, int l)
{
    unsigned long long a0 = 0ull, a1 = 0ull, a2 = 0ull, a3 = 0ull;
    unsigned long long b0 = 0ull, b1 = 0ull, b2 = 0ull, b3 = 0ull;
    const ulonglong2* pp = reinterpret_cast<const ulonglong2*>(vec32);
#pragma unroll
    for (int c = 0; c < 8; c += 2) {
        ulonglong2 v = pp[c];
        a0 = fma2(v.x, ea2[0 * 16 + 2 * c], a0); a0 = fma2(v.y, ea2[0 * 16 + 2 * c + 1], a0);
        a1 = fma2(v.x, ea2[1 * 16 + 2 * c], a1); a1 = fma2(v.y, ea2[1 * 16 + 2 * c + 1], a1);
        a2 = fma2(v.x, ea2[2 * 16 + 2 * c], a2); a2 = fma2(v.y, ea2[2 * 16 + 2 * c + 1], a2);
        a3 = fma2(v.x, ea2[3 * 16 + 2 * c], a3); a3 = fma2(v.y, ea2[3 * 16 + 2 * c + 1], a3);
        ulonglong2 u = pp[c + 1];
        b0 = fma2(u.x, ea2[0 * 16 + 2 * c + 2], b0); b0 = fma2(u.y, ea2[0 * 16 + 2 * c + 3], b0);
        b1 = fma2(u.x, ea2[1 * 16 + 2 * c + 2], b1); b1 = fma2(u.y, ea2[1 * 16 + 2 * c + 3], b1);
        b2 = fma2(u.x, ea2[2 * 16 + 2 * c + 2], b2); b2 = fma2(u.y, ea2[2 * 16 + 2 * c + 3], b2);
        b3 = fma2(u.x, ea2[3 * 16 + 2 * c + 2], b3); b3 = fma2(u.y, ea2[3 * 16 + 2 * c + 3], b3);
    }
    a0 = add2(a0, b0); a1 = add2(a1, b1); a2 = add2(a2, b2); a3 = add2(a3, b3);
    float4 po;
    po.x = red2(a0); po.y = red2(a1); po.z = red2(a2); po.w = red2(a3);
    *reinterpret_cast<float4*>(part + w * TAG + 4 * l) = po;
}

// ---- one interleaved score iteration (runs inside the scan's latency shadow)
__device__ __forceinline__ void score_iter(
    int j, int tid, float& acc,
    const int* __restrict__ yt, int stride,
    const float* __restrict__ ypb, const float* __restrict__ mrow,
    const float* __restrict__ A)
{
    int s = tid + (j << 8);                       // covers s in [0,1024)
    int tag = __ldg(yt + s * stride) & (TAG - 1);
    float m = __ldg(mrow + s);
    acc += __ldg(ypb + (size_t)s * TAG + tag) * m;
    if (s + 1 < SEQLEN) {
        int tag2 = __ldg(yt + (s + 1) * stride) & (TAG - 1);
        acc += __ldg(A + tag * TAG + tag2) * m * __ldg(mrow + (s + 1));
    }
}

// ---------------- forward step: alpha = m ? (EA^T alpha)*ey : alpha --------
template <int SLOT, int BUF, bool RENORM, bool PREP>
__device__ __forceinline__ void fwd_step(
    int i, int w, int l, int t, float& alpha, int& kacc,
    float (&eyp)[4], float (&mr)[4],
    const float* __restrict__ yprow, const float* __restrict__ mrow,
    const unsigned long long (&ea2)[64],
    float* __restrict__ asmv, float* __restrict__ partb, float* __restrict__ sb)
{
    // renorm factors, fully off the post-barrier chain (sb >=1 bar old)
    float k1 = eyp[SLOT], k2 = 1.0f;
    if (RENORM) {
        int kb = (__float_as_int(sb[0]) >> 23) & 0xff;
        float invc = __int_as_float((254 - kb) << 23);   // exact 2^(127-kb)
        kacc += 127 - kb;
        k1 *= invc; k2 = invc;
    }

    float* part = partb + BUF * 4 * TAG;
    spread(asmv + 32 * w, ea2, part, w, l);

    // prefetch step i+4's raw y_pred/mask (after spread issue, before bar)
    float yp_n = 0.0f, m_n = 1.0f;
    bool pf = (i + 4 <= MID);
    if (pf) {
        yp_n = __ldg(yprow + (i + 4) * TAG);
        m_n  = __ldg(mrow + (i + 4));
    }
    hbar(1);

    float s = (part[t] + part[TAG + t]) + (part[2 * TAG + t] + part[3 * TAG + t]);
    alpha = (mr[SLOT] > 0.5f) ? s * k1 : alpha * k2;
    asmv[t] = alpha;
    if (PREP && t == 0) sb[0] = alpha;
    eyp[SLOT] = pf ? __expf(yp_n) : 0.0f;
    mr[SLOT]  = m_n;
    __syncwarp();
}

// ---------------- backward step: beta = m ? EA@(ey_i*beta) : beta ----------
template <int SLOT, int BUF, bool RENORM, bool PREP>
__device__ __forceinline__ void bwd_step(
    int i, int w, int l, int t, float& beta, float& c, int& kacc,
    float (&eypub)[4], float (&mr)[4],
    const float* __restrict__ yprow, const float* __restrict__ mrow,
    const unsigned long long (&ea2)[64],
    float* __restrict__ asmv, float* __restrict__ partb, float* __restrict__ sb)
{
    float k2 = 1.0f;
    if (RENORM) {
        int kb = (__float_as_int(sb[1]) >> 23) & 0xff;
        k2 = __int_as_float((254 - kb) << 23);
        kacc += 127 - kb;
    }

    float* part = partb + BUF * 4 * TAG;
    spread(asmv + 32 * w, ea2, part, w, l);

    // prefetch step i-4's raw (mask, y_pred for ey_pub)
    float yp_n = 0.0f, m_n = 1.0f;
    bool pf = (i - 4 >= MID + 1);
    bool pfe = (i - 4 > MID + 1);
    if (pf) {
        m_n = __ldg(mrow + (i - 4));
        if (pfe) yp_n = __ldg(yprow + (i - 5) * TAG);
    }
    hbar(2);

    float s = (part[t] + part[TAG + t]) + (part[2 * TAG + t] + part[3 * TAG + t]);
    beta = (mr[SLOT] > 0.5f) ? s * k2 : beta * k2;
    c = beta * eypub[SLOT];
    asmv[t] = c;
    if (PREP && t == 0) sb[1] = c;
    eypub[SLOT] = pfe ? __expf(yp_n) : 1.0f;
    mr[SLOT]    = m_n;
    __syncwarp();
}

// ---------------- main kernel: 1 CTA (256 thr) per batch -------------------
__global__ void __launch_bounds__(256, 1)
crf_main_kernel(const float* __restrict__ y_pred,
                const int* __restrict__ y_true32,
                const float* __restrict__ mask,
                const float* __restrict__ A,
                float* __restrict__ out)
{
    const int tid = threadIdx.x;
    const int sub = tid >> 7;            // 0 = forward, 1 = backward
    const int t   = tid & (TAG - 1);
    const int w   = t >> 5;
    const int l   = t & 31;
    const int b   = blockIdx.x;

    __shared__ __align__(16) float s_asm[2][TAG];
    __shared__ __align__(16) float s_part[2][2 * 4 * TAG];  // [sub][buf*4*TAG]
    __shared__ float s_sb[2];
    __shared__ int   s_kacc[2];
    __shared__ float s_logZ;
    __shared__ int   s_is64;
    __shared__ int   s_last;

    float* asmv  = s_asm[sub];
    float* partb = s_part[sub];
    float* sb    = s_sb;

    const float* ypb   = y_pred + (size_t)b * SEQLEN * TAG;
    const float* yprow = ypb + t;
    const float* mrow  = mask + (size_t)b * SEQLEN;

    // ---- dtype detection in the PROLOGUE (one-time; frees the tail).
    // y_true is int32 under JAX default x64-disabled; detect genuine LE int64
    // (odd words of first 128 entries all zero <=> int64; tags are 0..127).
    if (tid == 0) s_is64 = 1;
    __syncthreads();
    if (tid < 128 && y_true32[2 * tid + 1] != 0) s_is64 = 0;
    __syncthreads();
    const int stride = s_is64 ? 2 : 1;
    const int* yt = y_true32 + (size_t)b * SEQLEN * stride;
    float score_acc = 0.0f;

    // ---- EA block (32 u x 4 outputs) in 64 packed regs ----
    unsigned long long ea2[64];
    const int u0 = 32 * w;
    if (sub == 0) {
#pragma unroll
        for (int j = 0; j < 4; j++)
#pragma unroll
            for (int k = 0; k < 16; k++) {
                float e0 = __expf(__ldg(A + (u0 + 2 * k)     * TAG + (4 * l + j)));
                float e1 = __expf(__ldg(A + (u0 + 2 * k + 1) * TAG + (4 * l + j)));
                ea2[j * 16 + k] = pack_f32x2(e0, e1);
            }
    } else {
#pragma unroll
        for (int j = 0; j < 4; j++)
#pragma unroll
            for (int k = 0; k < 16; k++) {
                float e0 = __expf(__ldg(A + (4 * l + j) * TAG + (u0 + 2 * k)));
                float e1 = __expf(__ldg(A + (4 * l + j) * TAG + (u0 + 2 * k + 1)));
                ea2[j * 16 + k] = pack_f32x2(e0, e1);
            }
    }

    int kacc = 0;
    float eyp[4], mr[4];

    if (sub == 0) {
        // ================= FORWARD: steps 1..512 =================
        float alpha = __expf(__ldg(yprow));    // alpha_0
        asmv[t] = alpha;
        if (t == 0) sb[0] = alpha;
#pragma unroll
        for (int j = 0; j < 4; j++) {
            eyp[j] = __expf(__ldg(yprow + (1 + j) * TAG));
            mr[j]  = __ldg(mrow + (1 + j));
        }
        hbar(1);   // cross-warp visibility of sb before window 0's early read

#pragma unroll 1
        for (int g = 0; g < 128; g++) {        // 128 groups; PREP at slot 2
            const int i = 1 + 4 * g;
            fwd_step<0, 0, true,  false>(i,     w, l, t, alpha, kacc, eyp, mr, yprow, mrow, ea2, asmv, partb, sb);
            fwd_step<1, 1, false, false>(i + 1, w, l, t, alpha, kacc, eyp, mr, yprow, mrow, ea2, asmv, partb, sb);
            fwd_step<2, 0, false, true >(i + 2, w, l, t, alpha, kacc, eyp, mr, yprow, mrow, ea2, asmv, partb, sb);
            fwd_step<3, 1, false, false>(i + 3, w, l, t, alpha, kacc, eyp, mr, yprow, mrow, ea2, asmv, partb, sb);
            // interleaved score: 4 iterations hidden in the scan's shadow
            if ((g & 31) == 1)
                score_iter(g >> 5, tid, score_acc, yt, stride, ypb, mrow, A);
        }
        if (t == 0) s_kacc[0] = kacc;
        // asmv holds alpha_512
    } else {
        // ================= BACKWARD: steps 1023..513 =================
        float beta = 1.0f;
        float c = __expf(__ldg(yprow + (SEQLEN - 1) * TAG));   // c_1023
        asmv[t] = c;
        if (t == 0) sb[1] = c;
#pragma unroll
        for (int j = 0; j < 4; j++) {
            mr[j]  = __ldg(mrow + (SEQLEN - 1 - j));
            eyp[j] = __expf(__ldg(yprow + (SEQLEN - 2 - j) * TAG));
        }
        hbar(2);   // cross-warp visibility of sb before window 0's early read

        // phase-shift: one dummy spread so bwd's FFMA bursts land inside fwd's
        // barrier/LDS windows. Junk input flows only into partial slots
        // overwritten by the first real spread before any post-hbar read.
        spread(partb + 4 * TAG + 32 * w, ea2, partb, w, l);

#pragma unroll 1
        for (int g = 0; g < 127; g++) {        // 127 groups: steps 1023..516
            const int i = SEQLEN - 1 - 4 * g;
            bwd_step<0, 0, true,  false>(i,     w, l, t, beta, c, kacc, eyp, mr, yprow, mrow, ea2, asmv, partb, sb);
            bwd_step<1, 1, false, false>(i - 1, w, l, t, beta, c, kacc, eyp, mr, yprow, mrow, ea2, asmv, partb, sb);
            bwd_step<2, 0, false, true >(i - 2, w, l, t, beta, c, kacc, eyp, mr, yprow, mrow, ea2, asmv, partb, sb);
            bwd_step<3, 1, false, false>(i - 3, w, l, t, beta, c, kacc, eyp, mr, yprow, mrow, ea2, asmv, partb, sb);
            if ((g & 31) == 1)
                score_iter(g >> 5, tid, score_acc, yt, stride, ypb, mrow, A);
        }
        // remainder: steps 515, 514, 513
        bwd_step<0, 0, true,  false>(MID + 3, w, l, t, beta, c, kacc, eyp, mr, yprow, mrow, ea2, asmv, partb, sb);
        bwd_step<1, 1, false, false>(MID + 2, w, l, t, beta, c, kacc, eyp, mr, yprow, mrow, ea2, asmv, partb, sb);
        bwd_step<2, 0, false, true >(MID + 1, w, l, t, beta, c, kacc, eyp, mr, yprow, mrow, ea2, asmv, partb, sb);
        if (t == 0) s_kacc[1] = kacc;
        // asmv holds beta_512 (ey_pub of step 513 was 1)
    }

    __syncthreads();   // join halves

    // ---- logZ = log(sum_t a_mid[t]*b_mid[t]) - (kf+kb)*ln2 ----
    if (tid < 32) {
        float v = 0.0f;
#pragma unroll
        for (int j = 0; j < 4; j++)
            v += s_asm[0][tid + 32 * j] * s_asm[1][tid + 32 * j];
#pragma unroll
        for (int o = 16; o > 0; o >>= 1)
            v += __shfl_xor_sync(0xffffffffu, v, o);
        if (tid == 0)
            s_logZ = logf(v) - (float)(s_kacc[0] + s_kacc[1]) * 0.69314718055994530942f;
    }

    // ---- reduce the (already-computed) score and finish ----
    float* red = &s_part[0][0];   // scratch (scan done)
    red[tid] = score_acc;
    __syncthreads();
    if (tid < 32) {
        float v = 0.0f;
#pragma unroll
        for (int j = 0; j < 8; j++) v += red[tid + 32 * j];
#pragma unroll
        for (int o = 16; o > 0; o >>= 1)
            v += __shfl_xor_sync(0xffffffffu, v, o);
        if (tid == 0) {
            g_red[b] = s_logZ - v;
            __threadfence();
            int done = atomicAdd(&g_count, 1);
            s_last = (done == BATCH - 1) ? 1 : 0;
        }
    }
    __syncthreads();

    // ---- last block: deterministic final mean over g_red, reset counter ----
    if (s_last) {
        __threadfence();   // acquire: make all g_red writes visible
        float v = (tid < 128) ? *((volatile float*)&g_red[tid]) : 0.0f;
        red[tid] = v;
        __syncthreads();
        if (tid < 32) {
            float s = red[tid] + red[tid + 32] + red[tid + 64] + red[tid + 96];
#pragma unroll
            for (int o = 16; o > 0; o >>= 1)
                s += __shfl_xor_sync(0xffffffffu, s, o);
            if (tid == 0) {
                out[0] = s * (1.0f / (float)BATCH);
                __threadfence();
                g_count = 0;   // replay-safe: restore initial device state
            }
        }
    }
}

// ---------------- launch ----------------
extern "C" void kernel_launch(void* const* d_in, const int* in_sizes, int n_in,
                              void* d_out, int out_size)
{
    const float* y_pred = nullptr;
    const float* A = nullptr;
    const int* y_true = nullptr;
    const float* mask = nullptr;
    for (int i = 0; i < n_in; i++) {
        long long sz = in_sizes[i];
        if (sz == (long long)BATCH * SEQLEN * TAG) {
            y_pred = (const float*)d_in[i];
        } else if (sz == (long long)TAG * TAG) {
            A = (const float*)d_in[i];
        } else if (sz == (long long)BATCH * SEQLEN) {
            if (!y_true) y_true = (const int*)d_in[i];
            else mask = (const float*)d_in[i];
        }
    }

    crf_main_kernel<<<BATCH, 256>>>(y_pred, y_true, mask, A, (float*)d_out);
}